// round 6
// baseline (speedup 1.0000x reference)
#include <cuda_runtime.h>

#define BB   8
#define LL   384
#define HH   512
#define NHH  8
#define DHH  64
#define MS   384
#define RROWS 769

// ---------------- scratch (device globals; no allocation allowed) ----------------
__device__ float g_q  [BB*LL*HH];
__device__ float g_k  [BB*LL*HH];
__device__ float g_vT [BB*NHH*DHH*LL];
__device__ float g_ctx[BB*LL*HH];
__device__ float g_R  [RROWS*HH];
__device__ float g_S  [BB*NHH*LL*LL];
__device__ float g_qR [BB*NHH*LL*RROWS];
__device__ float g_C  [BB*NHH*LL];
__device__ float g_D  [NHH*RROWS];
// rounded copies of raw inputs
__device__ float g_qin[BB*LL*HH];
__device__ float g_kin[BB*LL*HH];
__device__ float g_vin[BB*LL*HH];
__device__ float g_pe [RROWS*HH];
__device__ float g_Wq [HH*HH];
__device__ float g_Wk [HH*HH];
__device__ float g_Wv [HH*HH];
__device__ float g_Wr [HH*HH];
__device__ float g_Wff[HH*HH];

// ---------------- helpers ----------------
__device__ __forceinline__ float tf32r(float x) {
    unsigned u;
    asm("cvt.rna.tf32.f32 %0, %1;" : "=r"(u) : "f"(x));
    return __uint_as_float(u);
}

__device__ __forceinline__ void mma_tf32(float c[4],
                                         unsigned a0, unsigned a1, unsigned a2, unsigned a3,
                                         unsigned b0, unsigned b1)
{
    asm volatile(
        "mma.sync.aligned.m16n8k8.row.col.f32.tf32.tf32.f32 "
        "{%0,%1,%2,%3},{%4,%5,%6,%7},{%8,%9},{%0,%1,%2,%3};\n"
        : "+f"(c[0]), "+f"(c[1]), "+f"(c[2]), "+f"(c[3])
        : "r"(a0), "r"(a1), "r"(a2), "r"(a3), "r"(b0), "r"(b1));
}

__device__ __forceinline__ void cp16(unsigned dst, const void* src, bool pred) {
    int sz = pred ? 16 : 0;
    asm volatile("cp.async.cg.shared.global [%0], [%1], 16, %2;\n"
                 :: "r"(dst), "l"(src), "r"(sz));
}

// ---------------- pre-round pass: fp32 -> tf32(rna) copies ----------------
struct RSeg { const float* src; float* dst; int n4; };
struct RPack { RSeg s[9]; };

__global__ void round_inputs(RPack P)
{
    int idx = blockIdx.x * blockDim.x + threadIdx.x;
#pragma unroll
    for (int i = 0; i < 9; ++i) {
        if (idx < P.s[i].n4) {
            float4 v = ((const float4*)P.s[i].src)[idx];
            v.x = tf32r(v.x); v.y = tf32r(v.y); v.z = tf32r(v.z); v.w = tf32r(v.w);
            ((float4*)P.s[i].dst)[idx] = v;
            return;
        }
        idx -= P.s[i].n4;
    }
}

// ---------------- descriptor pack: several NT GEMMs in one launch ----------------
struct GDesc {
    const float* A; const float* B; const float* bias; float* C;
    int M, N, K, lda, ldb, ldc;
    long long Ao, Ai, Bo, Bi, Co, Ci;
    int bdiv;
    int zcount;
    int roundC;
    int transC;
    int skewB;
};
struct GPack { GDesc d[4]; };

static GDesc mkdesc(const float* A, const float* B, const float* bias, float* C,
                    int M, int N, int K, int lda, int ldb, int ldc,
                    long long Ao, long long Ai, long long Bo, long long Bi,
                    long long Co, long long Ci, int bdiv, int zcount,
                    int roundC, int transC, int skewB)
{
    GDesc d; d.A=A; d.B=B; d.bias=bias; d.C=C; d.M=M; d.N=N; d.K=K;
    d.lda=lda; d.ldb=ldb; d.ldc=ldc; d.Ao=Ao; d.Ai=Ai; d.Bo=Bo; d.Bi=Bi;
    d.Co=Co; d.Ci=Ci; d.bdiv=bdiv; d.zcount=zcount; d.roundC=roundC;
    d.transC=transC; d.skewB=skewB;
    return d;
}

// ---------------- tf32 tensor-core NT GEMM with cp.async double buffer ----------------
template<int BM, int BN, int WM, int WN>
__global__ void __launch_bounds__(256, 2)
gemm_tc(GPack P)
{
    constexpr int BK    = 32;
    constexpr int LDS_S = BK + 4;
    constexpr int WGM   = BM / WM;
    constexpr int MI    = WM / 16;
    constexpr int NI    = WN / 8;
    constexpr int ACH   = BM * (BK / 4) / 256;
    constexpr int BCH   = BN * (BK / 4) / 256;
    static_assert(WGM * (BN / WN) == 8, "8 warps");

    extern __shared__ float sm[];
    float* Asm = sm;
    float* Bsm = sm + 2 * BM * LDS_S;
    unsigned sb  = (unsigned)__cvta_generic_to_shared(sm);
    unsigned sbB = sb + 2u * BM * LDS_S * 4u;

    int zz = blockIdx.z;
    int di = 0;
    while (zz >= P.d[di].zcount) { zz -= P.d[di].zcount; ++di; }
    GDesc D = P.d[di];

    int bm = blockIdx.y * BM;
    int bn = blockIdx.x * BN;
    if (bm >= D.M || bn >= D.N) return;
    if (D.skewB) {
        int s = bm + bn;
        if (s + BM + BN - 2 < MS || s > MS + LL - 1) return;
    }

    const float* A = D.A + (long long)(zz / D.bdiv) * D.Ao + (long long)(zz % D.bdiv) * D.Ai;
    const float* B = D.B + (long long)(zz / D.bdiv) * D.Bo + (long long)(zz % D.bdiv) * D.Bi;
    float*       C = D.C + (long long)(zz / D.bdiv) * D.Co + (long long)(zz % D.bdiv) * D.Ci;

    int tid  = threadIdx.x;
    int lane = tid & 31;
    int wid  = tid >> 5;
    int wm   = (wid % WGM) * WM;
    int wn   = (wid / WGM) * WN;
    int r0   = lane >> 2;
    int c0   = lane & 3;

    float acc[MI][NI][4];
#pragma unroll
    for (int mi = 0; mi < MI; ++mi)
#pragma unroll
        for (int ni = 0; ni < NI; ++ni)
#pragma unroll
            for (int t = 0; t < 4; ++t) acc[mi][ni][t] = 0.f;

#define LOADSTAGE(T, BUF)                                                             \
    {                                                                                 \
        int kb = (T) * BK;                                                            \
        _Pragma("unroll")                                                             \
        for (int i = 0; i < ACH; ++i) {                                               \
            int e = tid + i * 256;                                                    \
            int row = e >> 3, kc = (e & 7) << 2;                                      \
            bool p = (bm + row) < D.M;                                                \
            const float* src = A + (long long)(bm + row) * D.lda + kb + kc;           \
            unsigned dst = sb + (((BUF) * BM + row) * LDS_S + kc) * 4u;               \
            cp16(dst, src, p);                                                        \
        }                                                                             \
        _Pragma("unroll")                                                             \
        for (int i = 0; i < BCH; ++i) {                                               \
            int e = tid + i * 256;                                                    \
            int row = e >> 3, kc = (e & 7) << 2;                                      \
            bool p = (bn + row) < D.N;                                                \
            const float* src = B + (long long)(bn + row) * D.ldb + kb + kc;           \
            unsigned dst = sbB + (((BUF) * BN + row) * LDS_S + kc) * 4u;              \
            cp16(dst, src, p);                                                        \
        }                                                                             \
        asm volatile("cp.async.commit_group;\n");                                     \
    }

#define MATH(BUF)                                                                     \
    _Pragma("unroll")                                                                 \
    for (int kk = 0; kk < BK; kk += 8) {                                              \
        unsigned a[MI][4], b[NI][2];                                                  \
        _Pragma("unroll")                                                             \
        for (int mi = 0; mi < MI; ++mi) {                                             \
            int m0 = wm + mi * 16 + r0;                                               \
            const unsigned* ap0 = (const unsigned*)(Asm + ((BUF) * BM + m0) * LDS_S + kk + c0);      \
            const unsigned* ap1 = (const unsigned*)(Asm + ((BUF) * BM + m0 + 8) * LDS_S + kk + c0);  \
            a[mi][0] = ap0[0];                                                        \
            a[mi][1] = ap1[0];                                                        \
            a[mi][2] = ap0[4];                                                        \
            a[mi][3] = ap1[4];                                                        \
        }                                                                             \
        _Pragma("unroll")                                                             \
        for (int ni = 0; ni < NI; ++ni) {                                             \
            int n0 = wn + ni * 8 + r0;                                                \
            const unsigned* bp = (const unsigned*)(Bsm + ((BUF) * BN + n0) * LDS_S + kk + c0);       \
            b[ni][0] = bp[0];                                                         \
            b[ni][1] = bp[4];                                                         \
        }                                                                             \
        _Pragma("unroll")                                                             \
        for (int mi = 0; mi < MI; ++mi)                                               \
            _Pragma("unroll")                                                         \
            for (int ni = 0; ni < NI; ++ni)                                           \
                mma_tf32(acc[mi][ni], a[mi][0], a[mi][1], a[mi][2], a[mi][3],         \
                         b[ni][0], b[ni][1]);                                         \
    }

    int nt = D.K / BK;
    LOADSTAGE(0, 0)

    for (int t = 0; t < nt; ++t) {
        int buf = t & 1;
        if (t + 1 < nt) {
            LOADSTAGE(t + 1, buf ^ 1)
            asm volatile("cp.async.wait_group 1;\n");
        } else {
            asm volatile("cp.async.wait_group 0;\n");
        }
        __syncthreads();
        MATH(buf)
        __syncthreads();
    }

#pragma unroll
    for (int mi = 0; mi < MI; ++mi) {
#pragma unroll
        for (int ni = 0; ni < NI; ++ni) {
            int cA = bn + wn + ni * 8 + c0 * 2;
            float b0 = 0.f, b1 = 0.f;
            if (D.bias) {
                if (cA < D.N)     b0 = D.bias[cA];
                if (cA + 1 < D.N) b1 = D.bias[cA + 1];
            }
#pragma unroll
            for (int half = 0; half < 2; ++half) {
                int r = bm + wm + mi * 16 + r0 + half * 8;
                if (r >= D.M) continue;
                float v0 = acc[mi][ni][half * 2]     + b0;
                float v1 = acc[mi][ni][half * 2 + 1] + b1;
                if (D.roundC) { v0 = tf32r(v0); v1 = tf32r(v1); }
                if (D.transC) {
                    long long base = (long long)(r / LL) * HH;
                    int j = r % LL;
                    if (cA < D.N)     C[(base + cA) * LL + j]     = v0;
                    if (cA + 1 < D.N) C[(base + cA + 1) * LL + j] = v1;
                } else {
                    if (cA < D.N)     C[(long long)r * D.ldc + cA]     = v0;
                    if (cA + 1 < D.N) C[(long long)r * D.ldc + cA + 1] = v1;
                }
            }
        }
    }
#undef LOADSTAGE
#undef MATH
}

// ---------------- small dot kernels ----------------
__global__ void dots_kernel(const float* __restrict__ u_bias, const float* __restrict__ v_bias)
{
    int idx = blockIdx.x * blockDim.x + threadIdx.x;
    const int NC = BB * NHH * LL;
    if (idx < NC) {
        int j = idx % LL;
        int h = (idx / LL) % NHH;
        int b = idx / (LL * NHH);
        const float* kp = g_k + ((long long)(b * LL + j) * NHH + h) * DHH;
        const float* up = u_bias + h * DHH;
        float s = 0.f;
#pragma unroll
        for (int d = 0; d < DHH; ++d) s += up[d] * kp[d];
        g_C[(b * NHH + h) * LL + j] = s;
    } else if (idx < NC + NHH * RROWS) {
        int id2 = idx - NC;
        int t = id2 % RROWS;
        int h = id2 / RROWS;
        const float* rp = g_R + (long long)t * HH + h * DHH;
        const float* vp = v_bias + h * DHH;
        float s = 0.f;
#pragma unroll
        for (int d = 0; d < DHH; ++d) s += vp[d] * rp[d];
        g_D[h * RROWS + t] = s;
    }
}

// ---------------- fused softmax + AV (flash-style) ----------------
// block = (i-tile of 64 rows) x (b,h). Streams 3 j-tiles of 128.
// Reads S (A-term), qR band, C, D; online softmax; P@vT accumulated in fragments.
#define F_IT 64
#define F_JT 128
#define F_LS (F_JT + 4)

__global__ void __launch_bounds__(256)
flash_av(const int* __restrict__ seq_len)
{
    extern __shared__ float sm[];
    float* Ps   = sm;                          // [F_IT][F_LS]
    float* Vs   = sm + F_IT * F_LS;            // [DHH][F_LS]
    float* mrow = sm + 2 * F_IT * F_LS;        // [F_IT]
    float* lrow = mrow + F_IT;
    float* frow = lrow + F_IT;

    int bh = blockIdx.y;                       // b*NHH + h
    int b  = bh / NHH;
    int h  = bh % NHH;
    int i0 = blockIdx.x * F_IT;
    int tid  = threadIdx.x;
    int lane = tid & 31;
    int wid  = tid >> 5;
    int sl = seq_len[b];

    const float* Sbase  = g_S  + (long long)bh * LL * LL;
    const float* qRbase = g_qR + (long long)bh * LL * RROWS;
    const float* Crow   = g_C  + bh * LL;
    const float* Drow   = g_D  + h * RROWS;
    const float* vTb    = g_vT + (long long)bh * DHH * LL;

    if (tid < F_IT) { mrow[tid] = -1e30f; lrow[tid] = 0.f; }
    __syncthreads();

    // elementwise mapping: quad per row, interleaved 4-float chunks
    int r   = tid >> 2;                 // 0..63 local row
    int q4  = tid & 3;                  // chunk selector
    int gi  = i0 + r;                   // global i

    // MMA mapping: warp tile 16 rows x 32 cols of O[64 x 64]
    int wm = (wid % 4) * 16;
    int wn = (wid / 4) * 32;
    int r0 = lane >> 2;
    int c0 = lane & 3;

    float acc[4][4];                    // NI=4 x 4
#pragma unroll
    for (int ni = 0; ni < 4; ++ni)
#pragma unroll
        for (int t = 0; t < 4; ++t) acc[ni][t] = 0.f;

    for (int jt = 0; jt < 3; ++jt) {
        int jb = jt * F_JT;
        if (jt > 0) __syncthreads();    // previous MMA done before overwriting Ps/Vs

        // load V tile: Vs[d][j] = vT[d][jb+j]
#pragma unroll
        for (int i = 0; i < 8; ++i) {
            int e = tid + i * 256;      // 2048 float4 slots
            int d  = e >> 5;            // 32 float4 per row
            int c4 = e & 31;
            float4 v = *(const float4*)(vTb + (long long)d * LL + jb + c4 * 4);
            *(float4*)(Vs + d * F_LS + c4 * 4) = v;
        }

        // scores for this thread's 32 columns
        float sc[32];
        float tmax = -1e30f;
        const float* Srow  = Sbase  + (long long)gi * LL + jb;
        const float* qRrow = qRbase + (long long)gi * RROWS;
#pragma unroll
        for (int k4 = 0; k4 < 8; ++k4) {
            int cbase = q4 * 4 + k4 * 16;
            float4 sv = *(const float4*)(Srow + cbase);
            float vv[4] = { sv.x, sv.y, sv.z, sv.w };
#pragma unroll
            for (int c = 0; c < 4; ++c) {
                int j = jb + cbase + c;
                int t = j - gi + MS;
                float val = (vv[c] + qRrow[t] + Crow[j] + Drow[t]) * 0.125f;
                if (j >= sl) val = -1e30f;
                sc[k4 * 4 + c] = val;
                tmax = fmaxf(tmax, val);
            }
        }
        // quad reduce max
        tmax = fmaxf(tmax, __shfl_xor_sync(0xffffffffu, tmax, 1));
        tmax = fmaxf(tmax, __shfl_xor_sync(0xffffffffu, tmax, 2));

        float m_old = mrow[r];
        float m_new = fmaxf(m_old, tmax);
        float f     = __expf(m_old - m_new);

        float tsum = 0.f;
#pragma unroll
        for (int k4 = 0; k4 < 8; ++k4) {
            int cbase = q4 * 4 + k4 * 16;
            float4 pv;
            float p0 = __expf(sc[k4 * 4 + 0] - m_new);
            float p1 = __expf(sc[k4 * 4 + 1] - m_new);
            float p2 = __expf(sc[k4 * 4 + 2] - m_new);
            float p3 = __expf(sc[k4 * 4 + 3] - m_new);
            tsum += p0 + p1 + p2 + p3;
            pv.x = tf32r(p0); pv.y = tf32r(p1); pv.z = tf32r(p2); pv.w = tf32r(p3);
            *(float4*)(Ps + r * F_LS + cbase) = pv;
        }
        tsum += __shfl_xor_sync(0xffffffffu, tsum, 1);
        tsum += __shfl_xor_sync(0xffffffffu, tsum, 2);

        if (q4 == 0) {
            lrow[r] = lrow[r] * f + tsum;
            mrow[r] = m_new;
            frow[r] = f;
        }
        __syncthreads();

        // rescale accumulators
        float f0 = frow[wm + r0];
        float f1 = frow[wm + r0 + 8];
#pragma unroll
        for (int ni = 0; ni < 4; ++ni) {
            acc[ni][0] *= f0; acc[ni][1] *= f0;
            acc[ni][2] *= f1; acc[ni][3] *= f1;
        }

        // MMA: O += P[64x128] @ V^T fragments (B rows = d)
#pragma unroll
        for (int kk = 0; kk < F_JT; kk += 8) {
            const unsigned* ap0 = (const unsigned*)(Ps + (wm + r0) * F_LS + kk + c0);
            const unsigned* ap1 = (const unsigned*)(Ps + (wm + r0 + 8) * F_LS + kk + c0);
            unsigned a0 = ap0[0], a1 = ap1[0], a2 = ap0[4], a3 = ap1[4];
#pragma unroll
            for (int ni = 0; ni < 4; ++ni) {
                const unsigned* bp = (const unsigned*)(Vs + (wn + ni * 8 + r0) * F_LS + kk + c0);
                mma_tf32(acc[ni], a0, a1, a2, a3, bp[0], bp[4]);
            }
        }
    }
    __syncthreads();

    // epilogue: ctx[b, i0+row, h*DHH + col] = tf32r(acc / l)
    float inv0 = 1.f / lrow[wm + r0];
    float inv1 = 1.f / lrow[wm + r0 + 8];
    float* ctxb = g_ctx + ((long long)(b * LL + i0) * HH) + h * DHH;
#pragma unroll
    for (int ni = 0; ni < 4; ++ni) {
        int col = wn + ni * 8 + c0 * 2;
        float* p0 = ctxb + (long long)(wm + r0) * HH + col;
        float* p1 = ctxb + (long long)(wm + r0 + 8) * HH + col;
        p0[0] = tf32r(acc[ni][0] * inv0);
        p0[1] = tf32r(acc[ni][1] * inv0);
        p1[0] = tf32r(acc[ni][2] * inv1);
        p1[1] = tf32r(acc[ni][3] * inv1);
    }
}

// ------------------------------------ launch ------------------------------------------
extern "C" void kernel_launch(void* const* d_in, const int* in_sizes, int n_in,
                              void* d_out, int out_size)
{
    const float* key    = (const float*)d_in[0];
    const float* query  = (const float*)d_in[1];
    const float* value  = (const float*)d_in[2];
    const int*   seqlen = (const int*)  d_in[3];
    const float* pe     = (const float*)d_in[4];
    const float* Wk = (const float*)d_in[5];  const float* bk = (const float*)d_in[6];
    const float* Wq = (const float*)d_in[7];  const float* bq = (const float*)d_in[8];
    const float* Wv = (const float*)d_in[9];  const float* bv = (const float*)d_in[10];
    const float* Wr = (const float*)d_in[11]; const float* br = (const float*)d_in[12];
    const float* u_bias = (const float*)d_in[13];
    const float* v_bias = (const float*)d_in[14];
    const float* Wff = (const float*)d_in[15]; const float* bff = (const float*)d_in[16];
    float* out = (float*)d_out;

    float *q_, *k_, *vT_, *ctx_, *R_, *S_, *qR_;
    float *qin_, *kin_, *vin_, *pe_, *Wq_, *Wk_, *Wv_, *Wr_, *Wff_;
    cudaGetSymbolAddress((void**)&q_,   g_q);
    cudaGetSymbolAddress((void**)&k_,   g_k);
    cudaGetSymbolAddress((void**)&vT_,  g_vT);
    cudaGetSymbolAddress((void**)&ctx_, g_ctx);
    cudaGetSymbolAddress((void**)&R_,   g_R);
    cudaGetSymbolAddress((void**)&S_,   g_S);
    cudaGetSymbolAddress((void**)&qR_,  g_qR);
    cudaGetSymbolAddress((void**)&qin_, g_qin);
    cudaGetSymbolAddress((void**)&kin_, g_kin);
    cudaGetSymbolAddress((void**)&vin_, g_vin);
    cudaGetSymbolAddress((void**)&pe_,  g_pe);
    cudaGetSymbolAddress((void**)&Wq_,  g_Wq);
    cudaGetSymbolAddress((void**)&Wk_,  g_Wk);
    cudaGetSymbolAddress((void**)&Wv_,  g_Wv);
    cudaGetSymbolAddress((void**)&Wr_,  g_Wr);
    cudaGetSymbolAddress((void**)&Wff_, g_Wff);

    const int M = BB * LL;   // 3072
    const size_t SH_BIG   = (size_t)(128 + 128) * 36 * 2 * 4;  // 73728
    const size_t SH_SMALL = (size_t)(64 + 128)  * 36 * 2 * 4;  // 55296
    const size_t SH_FLASH = (size_t)(2 * F_IT * F_LS + 3 * F_IT) * 4;  // 68352

    static bool attr_done = false;
    if (!attr_done) {
        cudaFuncSetAttribute(gemm_tc<128,128,64,32>,
                             cudaFuncAttributeMaxDynamicSharedMemorySize, (int)SH_BIG);
        cudaFuncSetAttribute(gemm_tc<64,128,32,32>,
                             cudaFuncAttributeMaxDynamicSharedMemorySize, (int)SH_SMALL);
        cudaFuncSetAttribute(flash_av,
                             cudaFuncAttributeMaxDynamicSharedMemorySize, (int)SH_FLASH);
        attr_done = true;
    }

    // ---- 0) round all fp32 inputs to tf32 once ----
    {
        const int NXL = BB * LL * HH / 4;
        const int NPE = RROWS * HH / 4;
        const int NW  = HH * HH / 4;
        RPack P;
        P.s[0] = { query, qin_, NXL };
        P.s[1] = { key,   kin_, NXL };
        P.s[2] = { value, vin_, NXL };
        P.s[3] = { pe,    pe_,  NPE };
        P.s[4] = { Wq,    Wq_,  NW  };
        P.s[5] = { Wk,    Wk_,  NW  };
        P.s[6] = { Wv,    Wv_,  NW  };
        P.s[7] = { Wr,    Wr_,  NW  };
        P.s[8] = { Wff,   Wff_, NW  };
        int tot = 3 * NXL + NPE + 5 * NW;
        round_inputs<<<(tot + 255) / 256, 256>>>(P);
    }

    // ---- 1) QKV + R projections (v writes vT directly) ----
    {
        GPack P;
        P.d[0] = mkdesc(qin_, Wq_, bq, q_,  M, HH, HH, HH, HH, HH, 0,0,0,0,0,0, 1, 1, 1, 0, 0);
        P.d[1] = mkdesc(kin_, Wk_, bk, k_,  M, HH, HH, HH, HH, HH, 0,0,0,0,0,0, 1, 1, 1, 0, 0);
        P.d[2] = mkdesc(vin_, Wv_, bv, vT_, M, HH, HH, HH, HH, HH, 0,0,0,0,0,0, 1, 1, 1, 1, 0);
        P.d[3] = mkdesc(pe_,  Wr_, br, R_,  RROWS, HH, HH, HH, HH, HH, 0,0,0,0,0,0, 1, 1, 1, 0, 0);
        dim3 g(HH / 128, (M + 127) / 128, 4);
        gemm_tc<128,128,64,32><<<g, 256, SH_BIG>>>(P);
    }

    // ---- 2) bias dots ----
    int ndots = BB * NHH * LL + NHH * RROWS;
    dots_kernel<<<(ndots + 255) / 256, 256>>>(u_bias, v_bias);

    // ---- 3) A-term + Bt-term in one launch (Bt uses skew-tile skip) ----
    {
        GPack P;
        P.d[0] = mkdesc(q_, k_, nullptr, S_, LL, LL, DHH, HH, HH, LL,
                        (long long)LL * HH, DHH,
                        (long long)LL * HH, DHH,
                        (long long)NHH * LL * LL, (long long)LL * LL, NHH, BB * NHH, 0, 0, 0);
        P.d[1] = mkdesc(q_, R_, nullptr, qR_, LL, RROWS, DHH, HH, HH, RROWS,
                        (long long)LL * HH, DHH,
                        0, DHH,
                        (long long)NHH * LL * RROWS, (long long)LL * RROWS, NHH, BB * NHH, 0, 0, 1);
        P.d[2] = P.d[1]; P.d[3] = P.d[1];
        dim3 g((RROWS + 127) / 128, LL / 128, 2 * BB * NHH);
        gemm_tc<128,128,64,32><<<g, 256, SH_BIG>>>(P);
    }

    // ---- 4) fused softmax + AV ----
    {
        dim3 g(LL / F_IT, BB * NHH);      // (6, 64)
        flash_av<<<g, 256, SH_FLASH>>>(seqlen);
    }

    // ---- 5) final FF: out = ctx @ Wff.T + bff  (64-row tiles -> 192 CTAs) ----
    {
        GPack P;
        P.d[0] = mkdesc(ctx_, Wff_, bff, out, M, HH, HH, HH, HH, HH, 0,0,0,0,0,0, 1, 1, 0, 0, 0);
        P.d[1] = P.d[0]; P.d[2] = P.d[0]; P.d[3] = P.d[0];
        dim3 g(HH / 128, (M + 63) / 64, 1);
        gemm_tc<64,128,32,32><<<g, 256, SH_SMALL>>>(P);
    }
}